// round 7
// baseline (speedup 1.0000x reference)
#include <cuda_runtime.h>

// RotateMyLayer: STN affine bilinear warp of ROIs from a batched feature map.
// feature_map: [8, 160, 160, 256] f32
// transform_matrixs: [10, 6] f32
// box_masks: [10] i32 (batch index per roi)
// box_widths: [10] i32
// out: [10, 8, 384, 256] f32

#define OUT_H   8
#define MAX_W   384
#define MAX_ROI 10
#define FH      160
#define FW      160
#define NC      256
#define NC4     (NC / 4)    // 64 float4 per pixel

__global__ __launch_bounds__(128) void stn_warp_kernel(
    const float* __restrict__ fm,
    const float* __restrict__ thetas,
    const int*   __restrict__ masks,
    const int*   __restrict__ widths,
    float*       __restrict__ out)
{
    // One warp per (roi, i, j) tuple; each lane handles 8 channels (2 float4).
    // grid = (96, 80), block = 128 (4 warps = 4 j-positions).
    const int warp = threadIdx.x >> 5;
    const int lane = threadIdx.x & 31;
    const int j    = blockIdx.x * 4 + warp;   // 0..383
    const int t    = blockIdx.y;              // 0..79  (= roi*8 + i)
    const int i    = t & 7;
    const int roi  = t >> 3;

    // 32-bit offsets everywhere (fm = 26M float4, out = 2M float4).
    float4* op = reinterpret_cast<float4*>(out)
               + (t * MAX_W + j) * NC4 + lane;

    const int w = __ldg(&widths[roi]);
    if (j >= w) {
        const float4 z = make_float4(0.f, 0.f, 0.f, 0.f);
        __stcs(&op[0],  z);   // streaming: output is write-once
        __stcs(&op[32], z);
        return;
    }

    const float2* th = reinterpret_cast<const float2*>(thetas + roi * 6);
    const float2 th0 = __ldg(&th[0]);   // t00, t01
    const float2 th1 = __ldg(&th[1]);   // t02, t10
    const float2 th2 = __ldg(&th[2]);   // t11, t12
    const int    b   = __ldg(&masks[roi]);

    const float denom = (float)((w - 1) > 1 ? (w - 1) : 1);
    const float x_t = -1.0f + 2.0f * __fdividef((float)j, denom);
    const float y_t = -1.0f + 2.0f * (float)i * (1.0f / 7.0f);

    const float xs = th0.x * x_t + th0.y * y_t + th1.x;
    const float ys = th1.y * x_t + th2.x * y_t + th2.y;
    const float x  = (xs + 1.0f) * (0.5f * (float)FW);
    const float y  = (ys + 1.0f) * (0.5f * (float)FH);

    const float x0f = floorf(x);
    const float y0f = floorf(y);
    const int x0 = min(max((int)x0f,     0), FW - 1);
    const int x1 = min(max((int)x0f + 1, 0), FW - 1);
    const int y0 = min(max((int)y0f,     0), FH - 1);
    const int y1 = min(max((int)y0f + 1, 0), FH - 1);

    // Addresses first -> issue all 8 LDG.128 ASAP.
    const float4* pa = reinterpret_cast<const float4*>(fm)
        + (b * (FH * FW) + y0 * FW + x0) * NC4 + lane;
    const int dRow = (y1 - y0) * (FW * NC4);   // 0 or FW*NC4
    const int dCol = (x1 - x0) * NC4;          // 0 or NC4

    const float4 Ia0 = pa[0];
    const float4 Ia1 = pa[32];
    const float4 Ib0 = pa[dRow];
    const float4 Ib1 = pa[dRow + 32];
    const float4 Ic0 = pa[dCol];
    const float4 Ic1 = pa[dCol + 32];
    const float4 Id0 = pa[dRow + dCol];
    const float4 Id1 = pa[dRow + dCol + 32];

    // Weight math lives in the load shadow.
    const float dx = x - x0f;
    const float dy = y - y0f;
    const float wa = (1.0f - dx) * (1.0f - dy);
    const float wb = (1.0f - dx) * dy;
    const float wc = dx * (1.0f - dy);
    const float wd = dx * dy;

    float4 r0, r1;
    r0.x = wa * Ia0.x + wb * Ib0.x + wc * Ic0.x + wd * Id0.x;
    r0.y = wa * Ia0.y + wb * Ib0.y + wc * Ic0.y + wd * Id0.y;
    r0.z = wa * Ia0.z + wb * Ib0.z + wc * Ic0.z + wd * Id0.z;
    r0.w = wa * Ia0.w + wb * Ib0.w + wc * Ic0.w + wd * Id0.w;
    r1.x = wa * Ia1.x + wb * Ib1.x + wc * Ic1.x + wd * Id1.x;
    r1.y = wa * Ia1.y + wb * Ib1.y + wc * Ic1.y + wd * Id1.y;
    r1.z = wa * Ia1.z + wb * Ib1.z + wc * Ic1.z + wd * Id1.z;
    r1.w = wa * Ia1.w + wb * Ib1.w + wc * Ic1.w + wd * Id1.w;

    __stcs(&op[0],  r0);
    __stcs(&op[32], r1);
}

extern "C" void kernel_launch(void* const* d_in, const int* in_sizes, int n_in,
                              void* d_out, int out_size)
{
    const float* fm     = (const float*)d_in[0];
    const float* thetas = (const float*)d_in[1];
    const int*   masks  = (const int*)d_in[2];
    const int*   widths = (const int*)d_in[3];
    float*       out    = (float*)d_out;

    dim3 grid(MAX_W / 4, MAX_ROI * OUT_H);   // (96, 80)
    stn_warp_kernel<<<grid, 128>>>(fm, thetas, masks, widths, out);
}

// round 8
// speedup vs baseline: 1.0030x; 1.0030x over previous
#include <cuda_runtime.h>

// RotateMyLayer: STN affine bilinear warp of ROIs from a batched feature map.
// feature_map: [8, 160, 160, 256] f32
// transform_matrixs: [10, 6] f32
// box_masks: [10] i32 (batch index per roi)
// box_widths: [10] i32
// out: [10, 8, 384, 256] f32

#define OUT_H   8
#define MAX_W   384
#define MAX_ROI 10
#define FH      160
#define FW      160
#define NC      256
#define NC4     (NC / 4)    // 64 float4 per pixel

// minBlocksPerMultiprocessor=11 -> reg budget ~46: lets all 8 LDG.128 stay
// in flight simultaneously (32 regs of payload + addressing) instead of
// being register-recycled into serial batches at the 32-reg allocation.
__global__ __launch_bounds__(128, 11) void stn_warp_kernel(
    const float* __restrict__ fm,
    const float* __restrict__ thetas,
    const int*   __restrict__ masks,
    const int*   __restrict__ widths,
    float*       __restrict__ out)
{
    // One warp per (roi, i, j) tuple; each lane handles 8 channels (2 float4).
    // grid = (96, 80), block = 128 (4 warps = 4 j-positions).
    const int warp = threadIdx.x >> 5;
    const int lane = threadIdx.x & 31;
    const int j    = blockIdx.x * 4 + warp;   // 0..383
    const int t    = blockIdx.y;              // 0..79  (= roi*8 + i)
    const int i    = t & 7;
    const int roi  = t >> 3;

    // 32-bit offsets everywhere (fm = 26M float4, out = 2M float4).
    float4* op = reinterpret_cast<float4*>(out)
               + (t * MAX_W + j) * NC4 + lane;

    const int w = __ldg(&widths[roi]);
    if (j >= w) {
        const float4 z = make_float4(0.f, 0.f, 0.f, 0.f);
        op[0]  = z;
        op[32] = z;
        return;
    }

    const float2* th = reinterpret_cast<const float2*>(thetas + roi * 6);
    const float2 th0 = __ldg(&th[0]);   // t00, t01
    const float2 th1 = __ldg(&th[1]);   // t02, t10
    const float2 th2 = __ldg(&th[2]);   // t11, t12
    const int    b   = __ldg(&masks[roi]);

    const float denom = (float)((w - 1) > 1 ? (w - 1) : 1);
    const float x_t = -1.0f + 2.0f * __fdividef((float)j, denom);
    const float y_t = -1.0f + 2.0f * (float)i * (1.0f / 7.0f);

    const float xs = th0.x * x_t + th0.y * y_t + th1.x;
    const float ys = th1.y * x_t + th2.x * y_t + th2.y;
    const float x  = (xs + 1.0f) * (0.5f * (float)FW);
    const float y  = (ys + 1.0f) * (0.5f * (float)FH);

    const float x0f = floorf(x);
    const float y0f = floorf(y);
    const int x0 = min(max((int)x0f,     0), FW - 1);
    const int x1 = min(max((int)x0f + 1, 0), FW - 1);
    const int y0 = min(max((int)y0f,     0), FH - 1);
    const int y1 = min(max((int)y0f + 1, 0), FH - 1);

    // Addresses first -> issue all 8 LDG.128 ASAP.
    const float4* pa = reinterpret_cast<const float4*>(fm)
        + (b * (FH * FW) + y0 * FW + x0) * NC4 + lane;
    const int dRow = (y1 - y0) * (FW * NC4);   // 0 or FW*NC4
    const int dCol = (x1 - x0) * NC4;          // 0 or NC4

    const float4 Ia0 = pa[0];
    const float4 Ia1 = pa[32];
    const float4 Ib0 = pa[dRow];
    const float4 Ib1 = pa[dRow + 32];
    const float4 Ic0 = pa[dCol];
    const float4 Ic1 = pa[dCol + 32];
    const float4 Id0 = pa[dRow + dCol];
    const float4 Id1 = pa[dRow + dCol + 32];

    // Weight math lives in the load shadow.
    const float dx = x - x0f;
    const float dy = y - y0f;
    const float wa = (1.0f - dx) * (1.0f - dy);
    const float wb = (1.0f - dx) * dy;
    const float wc = dx * (1.0f - dy);
    const float wd = dx * dy;

    float4 r0, r1;
    r0.x = wa * Ia0.x + wb * Ib0.x + wc * Ic0.x + wd * Id0.x;
    r0.y = wa * Ia0.y + wb * Ib0.y + wc * Ic0.y + wd * Id0.y;
    r0.z = wa * Ia0.z + wb * Ib0.z + wc * Ic0.z + wd * Id0.z;
    r0.w = wa * Ia0.w + wb * Ib0.w + wc * Ic0.w + wd * Id0.w;
    r1.x = wa * Ia1.x + wb * Ib1.x + wc * Ic1.x + wd * Id1.x;
    r1.y = wa * Ia1.y + wb * Ib1.y + wc * Ic1.y + wd * Id1.y;
    r1.z = wa * Ia1.z + wb * Ib1.z + wc * Ic1.z + wd * Id1.z;
    r1.w = wa * Ia1.w + wb * Ib1.w + wc * Ic1.w + wd * Id1.w;

    op[0]  = r0;
    op[32] = r1;
}

extern "C" void kernel_launch(void* const* d_in, const int* in_sizes, int n_in,
                              void* d_out, int out_size)
{
    const float* fm     = (const float*)d_in[0];
    const float* thetas = (const float*)d_in[1];
    const int*   masks  = (const int*)d_in[2];
    const int*   widths = (const int*)d_in[3];
    float*       out    = (float*)d_out;

    dim3 grid(MAX_W / 4, MAX_ROI * OUT_H);   // (96, 80)
    stn_warp_kernel<<<grid, 128>>>(fm, thetas, masks, widths, out);
}

// round 9
// speedup vs baseline: 1.0060x; 1.0030x over previous
#include <cuda_runtime.h>

// RotateMyLayer: STN affine bilinear warp of ROIs from a batched feature map.
// feature_map: [8, 160, 160, 256] f32
// transform_matrixs: [10, 6] f32
// box_masks: [10] i32 (batch index per roi)
// box_widths: [10] i32
// out: [10, 8, 384, 256] f32

#define OUT_H   8
#define MAX_W   384
#define MAX_ROI 10
#define FH      160
#define FW      160
#define NC      256
#define NC4     (NC / 4)    // 64 float4 per pixel

__global__ __launch_bounds__(128) void stn_warp_kernel(
    const float* __restrict__ fm,
    const float* __restrict__ thetas,
    const int*   __restrict__ masks,
    const int*   __restrict__ widths,
    float*       __restrict__ out)
{
    // One warp per (roi, i, j) tuple; each lane handles 8 channels (2 float4).
    // grid = (96, 80), block = 128 (4 warps = 4 j-positions).
    const int warp = threadIdx.x >> 5;
    const int lane = threadIdx.x & 31;
    const int j    = blockIdx.x * 4 + warp;   // 0..383
    const int t    = blockIdx.y;              // 0..79  (= roi*8 + i)
    const int i    = t & 7;
    const int roi  = t >> 3;

    // 32-bit offsets everywhere (fm = 26M float4, out = 2M float4).
    float4* op = reinterpret_cast<float4*>(out)
               + (t * MAX_W + j) * NC4 + lane;

    const int w = __ldg(&widths[roi]);
    if (j >= w) {
        const float4 z = make_float4(0.f, 0.f, 0.f, 0.f);
        op[0]  = z;
        op[32] = z;
        return;
    }

    const float2* th = reinterpret_cast<const float2*>(thetas + roi * 6);
    const float2 th0 = __ldg(&th[0]);   // t00, t01
    const float2 th1 = __ldg(&th[1]);   // t02, t10
    const float2 th2 = __ldg(&th[2]);   // t11, t12
    const int    b   = __ldg(&masks[roi]);

    const float denom = (float)((w - 1) > 1 ? (w - 1) : 1);
    const float x_t = -1.0f + 2.0f * __fdividef((float)j, denom);
    const float y_t = -1.0f + 2.0f * (float)i * (1.0f / 7.0f);

    const float xs = th0.x * x_t + th0.y * y_t + th1.x;
    const float ys = th1.y * x_t + th2.x * y_t + th2.y;
    const float x  = (xs + 1.0f) * (0.5f * (float)FW);
    const float y  = (ys + 1.0f) * (0.5f * (float)FH);

    const float x0f = floorf(x);
    const float y0f = floorf(y);
    const int x0 = min(max((int)x0f,     0), FW - 1);
    const int x1 = min(max((int)x0f + 1, 0), FW - 1);
    const int y0 = min(max((int)y0f,     0), FH - 1);
    const int y1 = min(max((int)y0f + 1, 0), FH - 1);

    const float4* pa = reinterpret_cast<const float4*>(fm)
        + (b * (FH * FW) + y0 * FW + x0) * NC4 + lane;
    const int dRow = (y1 - y0) * (FW * NC4);   // 0 or FW*NC4
    const int dCol = (x1 - x0) * NC4;          // 0 or NC4

    // ---- Batch 0: first float4 group (4 LDG.128 burst) ----
    const float4 Ia0 = pa[0];
    const float4 Ib0 = pa[dRow];
    const float4 Ic0 = pa[dCol];
    const float4 Id0 = pa[dRow + dCol];

    // Weight math in batch-0's load shadow.
    const float dx = x - x0f;
    const float dy = y - y0f;
    const float wa = (1.0f - dx) * (1.0f - dy);
    const float wb = (1.0f - dx) * dy;
    const float wc = dx * (1.0f - dy);
    const float wd = dx * dy;

    float4 r0;
    r0.x = wa * Ia0.x + wb * Ib0.x + wc * Ic0.x + wd * Id0.x;
    r0.y = wa * Ia0.y + wb * Ib0.y + wc * Ic0.y + wd * Id0.y;
    r0.z = wa * Ia0.z + wb * Ib0.z + wc * Ic0.z + wd * Id0.z;
    r0.w = wa * Ia0.w + wb * Ib0.w + wc * Ic0.w + wd * Id0.w;

    // Fence: keep batch-1 loads from being hoisted above batch-0 consumption,
    // halving the front-batched LDG burst depth (L1tex queue smoothing).
    asm volatile("" ::: "memory");

    // ---- Batch 1: second float4 group ----
    const float4 Ia1 = pa[32];
    const float4 Ib1 = pa[dRow + 32];
    const float4 Ic1 = pa[dCol + 32];
    const float4 Id1 = pa[dRow + dCol + 32];

    op[0] = r0;   // store r0 in batch-1's load shadow

    float4 r1;
    r1.x = wa * Ia1.x + wb * Ib1.x + wc * Ic1.x + wd * Id1.x;
    r1.y = wa * Ia1.y + wb * Ib1.y + wc * Ic1.y + wd * Id1.y;
    r1.z = wa * Ia1.z + wb * Ib1.z + wc * Ic1.z + wd * Id1.z;
    r1.w = wa * Ia1.w + wb * Ib1.w + wc * Ic1.w + wd * Id1.w;

    op[32] = r1;
}

extern "C" void kernel_launch(void* const* d_in, const int* in_sizes, int n_in,
                              void* d_out, int out_size)
{
    const float* fm     = (const float*)d_in[0];
    const float* thetas = (const float*)d_in[1];
    const int*   masks  = (const int*)d_in[2];
    const int*   widths = (const int*)d_in[3];
    float*       out    = (float*)d_out;

    dim3 grid(MAX_W / 4, MAX_ROI * OUT_H);   // (96, 80)
    stn_warp_kernel<<<grid, 128>>>(fm, thetas, masks, widths, out);
}